// round 10
// baseline (speedup 1.0000x reference)
#include <cuda_runtime.h>
#include <cuda_fp16.h>
#include <cstdint>

#define NUM_USERS 100000
#define NUM_ITEMS 200000
#define NUM_NODES (NUM_USERS + NUM_ITEMS)
#define DIM 64
#define NUM_EDGES 2000000
#define NFLOAT ((long)NUM_NODES * DIM)

#define ASSIGN_BS 512
#define DEG_BINS 64

// ---- device-global scratch ----
__device__ __half g_bufA[NFLOAT];            // x0 (fp16 copy of inputs)
__device__ __half g_bufB[NFLOAT];            // x1 (fp16)
__device__ __half g_bufC[NFLOAT];            // x2 (fp16)
__device__ int2   g_edges[NUM_EDGES];        // segment-grouped {dst, val bits}
// meta = [counts(NUM_NODES) | deghist(DEG_BINS) | total(1)]  — single memset
__device__ int    g_meta[NUM_NODES + DEG_BINS + 1];
__device__ int    g_off[NUM_NODES];          // segment base; after reorder = END
__device__ int    g_perm[NUM_NODES];         // nodes grouped by degree
__device__ int    g_degcursor[DEG_BINS];

#define g_counts  (g_meta)
#define g_deghist (g_meta + NUM_NODES)
#define g_total   (g_meta + NUM_NODES + DEG_BINS)

// ===========================================================================
// Prep: convert x0 -> fp16 A (8 lanes/node) AND build src-degree histogram.
// ===========================================================================
__global__ void k_prep_hist(const float4* __restrict__ user4,
                            const float4* __restrict__ item4,
                            uint4* __restrict__ a,
                            const int* __restrict__ esrc) {
    long t = (long)blockIdx.x * blockDim.x + threadIdx.x;
    if (t < NUM_EDGES) atomicAdd(&g_counts[esrc[t]], 1);

    long n = t >> 3;
    int  l = (int)(t & 7);
    if (n >= NUM_NODES) return;
    const float4* x0 = (n < NUM_USERS) ? (user4 + n * 16)
                                       : (item4 + (n - NUM_USERS) * 16);
    float4 m0 = __ldg(x0 + 2 * l);
    float4 m1 = __ldg(x0 + 2 * l + 1);
    uint4 o;
    *(__half2*)&o.x = __floats2half2_rn(m0.x, m0.y);
    *(__half2*)&o.y = __floats2half2_rn(m0.z, m0.w);
    *(__half2*)&o.z = __floats2half2_rn(m1.x, m1.y);
    *(__half2*)&o.w = __floats2half2_rn(m1.z, m1.w);
    __stcs(a + n * 8 + l, o);
}

// ===========================================================================
// Single-pass segment-base assignment + degree histogram.
// ===========================================================================
__global__ void k_assign() {
    __shared__ int sm[ASSIGN_BS];
    __shared__ int sh[DEG_BINS];
    __shared__ int s_base;
    if (threadIdx.x < DEG_BINS) sh[threadIdx.x] = 0;
    int i = blockIdx.x * ASSIGN_BS + threadIdx.x;
    int v = (i < NUM_NODES) ? g_counts[i] : 0;
    sm[threadIdx.x] = v; __syncthreads();
    if (i < NUM_NODES) {
        int bin = (v > DEG_BINS - 1) ? DEG_BINS - 1 : v;
        atomicAdd(&sh[bin], 1);
    }
    #pragma unroll
    for (int ofs = 1; ofs < ASSIGN_BS; ofs <<= 1) {
        int t = (threadIdx.x >= ofs) ? sm[threadIdx.x - ofs] : 0;
        __syncthreads();
        sm[threadIdx.x] += t;
        __syncthreads();
    }
    if (threadIdx.x == ASSIGN_BS - 1)
        s_base = atomicAdd(g_total, sm[ASSIGN_BS - 1]);
    __syncthreads();
    if (i < NUM_NODES) g_off[i] = s_base + sm[threadIdx.x] - v;  // exclusive base
    if (threadIdx.x < DEG_BINS && sh[threadIdx.x])
        atomicAdd(&g_deghist[threadIdx.x], sh[threadIdx.x]);
}

// Tiny serial scan of 64 degree bins -> bucket cursors.
__global__ void k_degscan() {
    __shared__ int sm[DEG_BINS];
    if (threadIdx.x < DEG_BINS) sm[threadIdx.x] = g_deghist[threadIdx.x];
    __syncthreads();
    if (threadIdx.x == 0) {
        int acc = 0;
        for (int i = 0; i < DEG_BINS; ++i) { int c = sm[i]; sm[i] = acc; acc += c; }
    }
    __syncthreads();
    if (threadIdx.x < DEG_BINS) g_degcursor[threadIdx.x] = sm[threadIdx.x];
}

// ===========================================================================
// Fused: (a) degree-bucket permutation (1 node/thread), (b) edge reorder
// (4 edges/thread: vector loads, 4 independent atomics in flight).
// Reorder bumps g_off so afterwards g_off[n] == segment END.
// ===========================================================================
__global__ void k_reorder_permute(const int4*  __restrict__ esrc4,
                                  const int4*  __restrict__ edst4,
                                  const float4* __restrict__ eval4) {
    __shared__ int s_hist[DEG_BINS];
    __shared__ int s_base[DEG_BINS];
    if (threadIdx.x < DEG_BINS) s_hist[threadIdx.x] = 0;
    __syncthreads();
    long t = (long)blockIdx.x * blockDim.x + threadIdx.x;
    int bin = 0, rank = 0;
    bool node_ok = (t < NUM_NODES);
    if (node_ok) {
        int d = g_counts[t]; bin = (d > DEG_BINS - 1) ? DEG_BINS - 1 : d;
        rank = atomicAdd(&s_hist[bin], 1);
    }
    __syncthreads();
    if (threadIdx.x < DEG_BINS && s_hist[threadIdx.x])
        s_base[threadIdx.x] = atomicAdd(&g_degcursor[threadIdx.x], s_hist[threadIdx.x]);
    __syncthreads();
    if (node_ok) g_perm[s_base[bin] + rank] = (int)t;

    if (t < NUM_EDGES / 4) {
        int4   s = __ldg(esrc4 + t);
        int4   d = __ldg(edst4 + t);
        float4 v = __ldg(eval4 + t);
        int p0 = atomicAdd(&g_off[s.x], 1);   // 4 independent ATOMG in flight
        int p1 = atomicAdd(&g_off[s.y], 1);
        int p2 = atomicAdd(&g_off[s.z], 1);
        int p3 = atomicAdd(&g_off[s.w], 1);
        __stcs(&g_edges[p0], make_int2(d.x, __float_as_int(v.x)));
        __stcs(&g_edges[p1], make_int2(d.y, __float_as_int(v.y)));
        __stcs(&g_edges[p2], make_int2(d.z, __float_as_int(v.z)));
        __stcs(&g_edges[p3], make_int2(d.w, __float_as_int(v.w)));
    }
}

// ===========================================================================
// Segmented-sum layers: 8 lanes/node, fp32 accumulation, fp16 rows,
// 8/4/2/1-wide unroll ladder for MLP (degree-uniform warps), no atomics.
// ===========================================================================
__device__ __forceinline__ void acc_h8(uint4 r, float v, float* a) {
    float2 f;
    f = __half22float2(*(const __half2*)&r.x); a[0] += f.x * v; a[1] += f.y * v;
    f = __half22float2(*(const __half2*)&r.y); a[2] += f.x * v; a[3] += f.y * v;
    f = __half22float2(*(const __half2*)&r.z); a[4] += f.x * v; a[5] += f.y * v;
    f = __half22float2(*(const __half2*)&r.w); a[6] += f.x * v; a[7] += f.y * v;
}

__device__ __forceinline__ uint4 pack_h8(const float* a) {
    uint4 o;
    *(__half2*)&o.x = __floats2half2_rn(a[0], a[1]);
    *(__half2*)&o.y = __floats2half2_rn(a[2], a[3]);
    *(__half2*)&o.z = __floats2half2_rn(a[4], a[5]);
    *(__half2*)&o.w = __floats2half2_rn(a[6], a[7]);
    return o;
}

__device__ __forceinline__ void seg_sum(const uint4* __restrict__ x,
                                        int beg, int end, int l, float* a) {
    int p = beg;
    for (; p + 8 <= end; p += 8) {
        int2 e[8]; uint4 r[8];
        #pragma unroll
        for (int k = 0; k < 8; ++k) e[k] = __ldg(&g_edges[p + k]);
        #pragma unroll
        for (int k = 0; k < 8; ++k) r[k] = __ldg(x + (long)e[k].x * 8 + l);
        #pragma unroll
        for (int k = 0; k < 8; ++k) acc_h8(r[k], __int_as_float(e[k].y), a);
    }
    if (p + 4 <= end) {
        int2 e[4]; uint4 r[4];
        #pragma unroll
        for (int k = 0; k < 4; ++k) e[k] = __ldg(&g_edges[p + k]);
        #pragma unroll
        for (int k = 0; k < 4; ++k) r[k] = __ldg(x + (long)e[k].x * 8 + l);
        #pragma unroll
        for (int k = 0; k < 4; ++k) acc_h8(r[k], __int_as_float(e[k].y), a);
        p += 4;
    }
    if (p + 2 <= end) {
        int2 e0 = __ldg(&g_edges[p]);
        int2 e1 = __ldg(&g_edges[p + 1]);
        uint4 r0 = __ldg(x + (long)e0.x * 8 + l);
        uint4 r1 = __ldg(x + (long)e1.x * 8 + l);
        acc_h8(r0, __int_as_float(e0.y), a);
        acc_h8(r1, __int_as_float(e1.y), a);
        p += 2;
    }
    if (p < end) {
        int2 e = __ldg(&g_edges[p]);
        uint4 r = __ldg(x + (long)e.x * 8 + l);
        acc_h8(r, __int_as_float(e.y), a);
    }
}

// Generic layer: fp16 x -> fp16 y   (layers 1 and 2)
__global__ void k_layer(const uint4* __restrict__ x,
                        uint4* __restrict__ y) {
    long t = (long)blockIdx.x * blockDim.x + threadIdx.x;
    long g = t >> 3;
    int  l = (int)(t & 7);
    if (g >= NUM_NODES) return;
    int n = g_perm[g];
    int end = g_off[n];
    int beg = end - g_counts[n];

    float a[8] = {0.f,0.f,0.f,0.f,0.f,0.f,0.f,0.f};
    seg_sum(x, beg, end, l, a);
    __stcs(y + (long)n * 8 + l, pack_h8(a));
}

// Layer 3 + fused epilogue: out = (x0_fp32 + B + C + x3)/4
__global__ void k_layer3_final(const uint4* __restrict__ x,      // C (x2)
                               const float4* __restrict__ user4,
                               const float4* __restrict__ item4,
                               const uint4* __restrict__ b,      // B (x1)
                               float4* __restrict__ out4) {
    long t = (long)blockIdx.x * blockDim.x + threadIdx.x;
    long g = t >> 3;
    int  l = (int)(t & 7);
    if (g >= NUM_NODES) return;
    int n = g_perm[g];
    int end = g_off[n];
    int beg = end - g_counts[n];

    float a[8] = {0.f,0.f,0.f,0.f,0.f,0.f,0.f,0.f};
    seg_sum(x, beg, end, l, a);

    const float4* x0 = (n < NUM_USERS) ? (user4 + (long)n * 16)
                                       : (item4 + (long)(n - NUM_USERS) * 16);
    float4 e0 = __ldg(x0 + 2 * l);
    float4 e1 = __ldg(x0 + 2 * l + 1);
    uint4 br = __ldg(b + (long)n * 8 + l);
    uint4 cr = __ldg(x + (long)n * 8 + l);
    float bb[8], cc[8];
    {
        float2 f;
        f = __half22float2(*(const __half2*)&br.x); bb[0]=f.x; bb[1]=f.y;
        f = __half22float2(*(const __half2*)&br.y); bb[2]=f.x; bb[3]=f.y;
        f = __half22float2(*(const __half2*)&br.z); bb[4]=f.x; bb[5]=f.y;
        f = __half22float2(*(const __half2*)&br.w); bb[6]=f.x; bb[7]=f.y;
        f = __half22float2(*(const __half2*)&cr.x); cc[0]=f.x; cc[1]=f.y;
        f = __half22float2(*(const __half2*)&cr.y); cc[2]=f.x; cc[3]=f.y;
        f = __half22float2(*(const __half2*)&cr.z); cc[4]=f.x; cc[5]=f.y;
        f = __half22float2(*(const __half2*)&cr.w); cc[6]=f.x; cc[7]=f.y;
    }
    float4 o0, o1;
    o0.x = (a[0] + e0.x + bb[0] + cc[0]) * 0.25f;
    o0.y = (a[1] + e0.y + bb[1] + cc[1]) * 0.25f;
    o0.z = (a[2] + e0.z + bb[2] + cc[2]) * 0.25f;
    o0.w = (a[3] + e0.w + bb[3] + cc[3]) * 0.25f;
    o1.x = (a[4] + e1.x + bb[4] + cc[4]) * 0.25f;
    o1.y = (a[5] + e1.y + bb[5] + cc[5]) * 0.25f;
    o1.z = (a[6] + e1.z + bb[6] + cc[6]) * 0.25f;
    o1.w = (a[7] + e1.w + bb[7] + cc[7]) * 0.25f;
    __stcs(out4 + (long)n * 16 + 2 * l,     o0);
    __stcs(out4 + (long)n * 16 + 2 * l + 1, o1);
}

// ===========================================================================
extern "C" void kernel_launch(void* const* d_in, const int* in_sizes, int n_in,
                              void* d_out, int out_size) {
    const float4* user4 = (const float4*)d_in[0];
    const float4* item4 = (const float4*)d_in[1];
    const float*  eval  = (const float*) d_in[2];
    const int*    esrc  = (const int*)   d_in[3];
    const int*    edst  = (const int*)   d_in[4];
    float4*       out4  = (float4*)d_out;

    void *pA, *pB, *pC, *pMeta;
    cudaGetSymbolAddress(&pA,    g_bufA);
    cudaGetSymbolAddress(&pB,    g_bufB);
    cudaGetSymbolAddress(&pC,    g_bufC);
    cudaGetSymbolAddress(&pMeta, g_meta);
    uint4* A = (uint4*)pA;
    uint4* B = (uint4*)pB;
    uint4* C = (uint4*)pC;

    const int TB = 256;
    const unsigned group_blocks  = (unsigned)(((long)NUM_NODES * 8 + TB - 1) / TB); // 9375
    const unsigned fuse_blocks   = (NUM_EDGES / 4 + TB - 1) / TB;                   // 1954
    const unsigned assign_blocks = (NUM_NODES + ASSIGN_BS - 1) / ASSIGN_BS;         // 586

    // --- prep ---
    cudaMemsetAsync(pMeta, 0, (NUM_NODES + DEG_BINS + 1) * sizeof(int));
    k_prep_hist      <<<group_blocks, TB>>>(user4, item4, A, esrc);
    k_assign         <<<assign_blocks, ASSIGN_BS>>>();
    k_degscan        <<<1, DEG_BINS>>>();
    k_reorder_permute<<<fuse_blocks, TB>>>((const int4*)esrc, (const int4*)edst,
                                           (const float4*)eval);

    // --- 3 propagation layers ---
    k_layer       <<<group_blocks, TB>>>(A, B);
    k_layer       <<<group_blocks, TB>>>(B, C);
    k_layer3_final<<<group_blocks, TB>>>(C, user4, item4, B, out4);
}

// round 12
// speedup vs baseline: 1.1382x; 1.1382x over previous
#include <cuda_runtime.h>
#include <cuda_fp16.h>
#include <cstdint>

#define NUM_USERS 100000
#define NUM_ITEMS 200000
#define NUM_NODES (NUM_USERS + NUM_ITEMS)
#define DIM 64
#define NUM_EDGES 2000000
#define NFLOAT ((long)NUM_NODES * DIM)

#define ASSIGN_BS 512
#define DEG_BINS 64

// ---- device-global scratch ----
__device__ __half g_bufA[NFLOAT];            // x0 (fp16 copy of inputs)
__device__ __half g_bufB[NFLOAT];            // x1 (fp16)
__device__ __half g_bufC[NFLOAT];            // x2 (fp16)
__device__ int2   g_edges[NUM_EDGES];        // segment-grouped {dst, val bits}
// meta = [counts(NUM_NODES) | deghist(DEG_BINS) | total(1)]  — single memset
__device__ int    g_meta[NUM_NODES + DEG_BINS + 1];
__device__ int    g_off[NUM_NODES];          // segment base; after reorder = END
__device__ int    g_perm[NUM_NODES];         // nodes grouped by degree
__device__ int    g_degcursor[DEG_BINS];

#define g_counts  (g_meta)
#define g_deghist (g_meta + NUM_NODES)
#define g_total   (g_meta + NUM_NODES + DEG_BINS)

// ===========================================================================
// Prep: convert x0 -> fp16 A (8 lanes/node) AND build src-degree histogram.
// ===========================================================================
__global__ void k_prep_hist(const float4* __restrict__ user4,
                            const float4* __restrict__ item4,
                            uint4* __restrict__ a,
                            const int* __restrict__ esrc) {
    long t = (long)blockIdx.x * blockDim.x + threadIdx.x;
    if (t < NUM_EDGES) atomicAdd(&g_counts[esrc[t]], 1);

    long n = t >> 3;
    int  l = (int)(t & 7);
    if (n >= NUM_NODES) return;
    const float4* x0 = (n < NUM_USERS) ? (user4 + n * 16)
                                       : (item4 + (n - NUM_USERS) * 16);
    float4 m0 = __ldg(x0 + 2 * l);
    float4 m1 = __ldg(x0 + 2 * l + 1);
    uint4 o;
    *(__half2*)&o.x = __floats2half2_rn(m0.x, m0.y);
    *(__half2*)&o.y = __floats2half2_rn(m0.z, m0.w);
    *(__half2*)&o.z = __floats2half2_rn(m1.x, m1.y);
    *(__half2*)&o.w = __floats2half2_rn(m1.z, m1.w);
    __stcs(a + n * 8 + l, o);
}

// ===========================================================================
// Single-pass segment-base assignment + degree histogram.
// ===========================================================================
__global__ void k_assign() {
    __shared__ int sm[ASSIGN_BS];
    __shared__ int sh[DEG_BINS];
    __shared__ int s_base;
    if (threadIdx.x < DEG_BINS) sh[threadIdx.x] = 0;
    int i = blockIdx.x * ASSIGN_BS + threadIdx.x;
    int v = (i < NUM_NODES) ? g_counts[i] : 0;
    sm[threadIdx.x] = v; __syncthreads();
    if (i < NUM_NODES) {
        int bin = (v > DEG_BINS - 1) ? DEG_BINS - 1 : v;
        atomicAdd(&sh[bin], 1);
    }
    #pragma unroll
    for (int ofs = 1; ofs < ASSIGN_BS; ofs <<= 1) {
        int t = (threadIdx.x >= ofs) ? sm[threadIdx.x - ofs] : 0;
        __syncthreads();
        sm[threadIdx.x] += t;
        __syncthreads();
    }
    if (threadIdx.x == ASSIGN_BS - 1)
        s_base = atomicAdd(g_total, sm[ASSIGN_BS - 1]);
    __syncthreads();
    if (i < NUM_NODES) g_off[i] = s_base + sm[threadIdx.x] - v;  // exclusive base
    if (threadIdx.x < DEG_BINS && sh[threadIdx.x])
        atomicAdd(&g_deghist[threadIdx.x], sh[threadIdx.x]);
}

// Tiny serial scan of 64 degree bins -> bucket cursors.
__global__ void k_degscan() {
    __shared__ int sm[DEG_BINS];
    if (threadIdx.x < DEG_BINS) sm[threadIdx.x] = g_deghist[threadIdx.x];
    __syncthreads();
    if (threadIdx.x == 0) {
        int acc = 0;
        for (int i = 0; i < DEG_BINS; ++i) { int c = sm[i]; sm[i] = acc; acc += c; }
    }
    __syncthreads();
    if (threadIdx.x < DEG_BINS) g_degcursor[threadIdx.x] = sm[threadIdx.x];
}

// ===========================================================================
// Fused: (a) degree-bucket permutation (1 node/thread), (b) edge reorder
// (2 edges/thread: MLP=2 atomics while keeping 1M threads in flight).
// Reorder bumps g_off so afterwards g_off[n] == segment END.
// ===========================================================================
__global__ void k_reorder_permute(const int2*  __restrict__ esrc2,
                                  const int2*  __restrict__ edst2,
                                  const float2* __restrict__ eval2) {
    __shared__ int s_hist[DEG_BINS];
    __shared__ int s_base[DEG_BINS];
    if (threadIdx.x < DEG_BINS) s_hist[threadIdx.x] = 0;
    __syncthreads();
    long t = (long)blockIdx.x * blockDim.x + threadIdx.x;
    int bin = 0, rank = 0;
    bool node_ok = (t < NUM_NODES);
    if (node_ok) {
        int d = g_counts[t]; bin = (d > DEG_BINS - 1) ? DEG_BINS - 1 : d;
        rank = atomicAdd(&s_hist[bin], 1);
    }
    __syncthreads();
    if (threadIdx.x < DEG_BINS && s_hist[threadIdx.x])
        s_base[threadIdx.x] = atomicAdd(&g_degcursor[threadIdx.x], s_hist[threadIdx.x]);
    __syncthreads();
    if (node_ok) g_perm[s_base[bin] + rank] = (int)t;

    if (t < NUM_EDGES / 2) {
        int2   s = __ldg(esrc2 + t);
        int2   d = __ldg(edst2 + t);
        float2 v = __ldg(eval2 + t);
        int p0 = atomicAdd(&g_off[s.x], 1);   // 2 independent ATOMG in flight
        int p1 = atomicAdd(&g_off[s.y], 1);
        __stcs(&g_edges[p0], make_int2(d.x, __float_as_int(v.x)));
        __stcs(&g_edges[p1], make_int2(d.y, __float_as_int(v.y)));
    }
}

// ===========================================================================
// Segmented-sum layers: 8 lanes/node, fp32 accumulation, fp16 rows,
// 4/2/1-wide unroll ladder (proven R9 config), no atomics.
// ===========================================================================
__device__ __forceinline__ void acc_h8(uint4 r, float v, float* a) {
    float2 f;
    f = __half22float2(*(const __half2*)&r.x); a[0] += f.x * v; a[1] += f.y * v;
    f = __half22float2(*(const __half2*)&r.y); a[2] += f.x * v; a[3] += f.y * v;
    f = __half22float2(*(const __half2*)&r.z); a[4] += f.x * v; a[5] += f.y * v;
    f = __half22float2(*(const __half2*)&r.w); a[6] += f.x * v; a[7] += f.y * v;
}

__device__ __forceinline__ uint4 pack_h8(const float* a) {
    uint4 o;
    *(__half2*)&o.x = __floats2half2_rn(a[0], a[1]);
    *(__half2*)&o.y = __floats2half2_rn(a[2], a[3]);
    *(__half2*)&o.z = __floats2half2_rn(a[4], a[5]);
    *(__half2*)&o.w = __floats2half2_rn(a[6], a[7]);
    return o;
}

__device__ __forceinline__ void seg_sum(const uint4* __restrict__ x,
                                        int beg, int end, int l, float* a) {
    int p = beg;
    for (; p + 4 <= end; p += 4) {
        int2 e0 = __ldg(&g_edges[p]);
        int2 e1 = __ldg(&g_edges[p + 1]);
        int2 e2 = __ldg(&g_edges[p + 2]);
        int2 e3 = __ldg(&g_edges[p + 3]);
        uint4 r0 = __ldg(x + (long)e0.x * 8 + l);
        uint4 r1 = __ldg(x + (long)e1.x * 8 + l);
        uint4 r2 = __ldg(x + (long)e2.x * 8 + l);
        uint4 r3 = __ldg(x + (long)e3.x * 8 + l);
        acc_h8(r0, __int_as_float(e0.y), a);
        acc_h8(r1, __int_as_float(e1.y), a);
        acc_h8(r2, __int_as_float(e2.y), a);
        acc_h8(r3, __int_as_float(e3.y), a);
    }
    if (p + 2 <= end) {
        int2 e0 = __ldg(&g_edges[p]);
        int2 e1 = __ldg(&g_edges[p + 1]);
        uint4 r0 = __ldg(x + (long)e0.x * 8 + l);
        uint4 r1 = __ldg(x + (long)e1.x * 8 + l);
        acc_h8(r0, __int_as_float(e0.y), a);
        acc_h8(r1, __int_as_float(e1.y), a);
        p += 2;
    }
    if (p < end) {
        int2 e = __ldg(&g_edges[p]);
        uint4 r = __ldg(x + (long)e.x * 8 + l);
        acc_h8(r, __int_as_float(e.y), a);
    }
}

// Generic layer: fp16 x -> fp16 y   (layers 1 and 2)
__global__ void k_layer(const uint4* __restrict__ x,
                        uint4* __restrict__ y) {
    long t = (long)blockIdx.x * blockDim.x + threadIdx.x;
    long g = t >> 3;
    int  l = (int)(t & 7);
    if (g >= NUM_NODES) return;
    int n = g_perm[g];
    int end = g_off[n];
    int beg = end - g_counts[n];

    float a[8] = {0.f,0.f,0.f,0.f,0.f,0.f,0.f,0.f};
    seg_sum(x, beg, end, l, a);
    __stcs(y + (long)n * 8 + l, pack_h8(a));
}

// Layer 3 + fused epilogue: out = (x0_fp32 + B + C + x3)/4
__global__ void k_layer3_final(const uint4* __restrict__ x,      // C (x2)
                               const float4* __restrict__ user4,
                               const float4* __restrict__ item4,
                               const uint4* __restrict__ b,      // B (x1)
                               float4* __restrict__ out4) {
    long t = (long)blockIdx.x * blockDim.x + threadIdx.x;
    long g = t >> 3;
    int  l = (int)(t & 7);
    if (g >= NUM_NODES) return;
    int n = g_perm[g];
    int end = g_off[n];
    int beg = end - g_counts[n];

    float a[8] = {0.f,0.f,0.f,0.f,0.f,0.f,0.f,0.f};
    seg_sum(x, beg, end, l, a);

    const float4* x0 = (n < NUM_USERS) ? (user4 + (long)n * 16)
                                       : (item4 + (long)(n - NUM_USERS) * 16);
    float4 e0 = __ldg(x0 + 2 * l);
    float4 e1 = __ldg(x0 + 2 * l + 1);
    uint4 br = __ldg(b + (long)n * 8 + l);
    uint4 cr = __ldg(x + (long)n * 8 + l);
    float bb[8], cc[8];
    {
        float2 f;
        f = __half22float2(*(const __half2*)&br.x); bb[0]=f.x; bb[1]=f.y;
        f = __half22float2(*(const __half2*)&br.y); bb[2]=f.x; bb[3]=f.y;
        f = __half22float2(*(const __half2*)&br.z); bb[4]=f.x; bb[5]=f.y;
        f = __half22float2(*(const __half2*)&br.w); bb[6]=f.x; bb[7]=f.y;
        f = __half22float2(*(const __half2*)&cr.x); cc[0]=f.x; cc[1]=f.y;
        f = __half22float2(*(const __half2*)&cr.y); cc[2]=f.x; cc[3]=f.y;
        f = __half22float2(*(const __half2*)&cr.z); cc[4]=f.x; cc[5]=f.y;
        f = __half22float2(*(const __half2*)&cr.w); cc[6]=f.x; cc[7]=f.y;
    }
    float4 o0, o1;
    o0.x = (a[0] + e0.x + bb[0] + cc[0]) * 0.25f;
    o0.y = (a[1] + e0.y + bb[1] + cc[1]) * 0.25f;
    o0.z = (a[2] + e0.z + bb[2] + cc[2]) * 0.25f;
    o0.w = (a[3] + e0.w + bb[3] + cc[3]) * 0.25f;
    o1.x = (a[4] + e1.x + bb[4] + cc[4]) * 0.25f;
    o1.y = (a[5] + e1.y + bb[5] + cc[5]) * 0.25f;
    o1.z = (a[6] + e1.z + bb[6] + cc[6]) * 0.25f;
    o1.w = (a[7] + e1.w + bb[7] + cc[7]) * 0.25f;
    __stcs(out4 + (long)n * 16 + 2 * l,     o0);
    __stcs(out4 + (long)n * 16 + 2 * l + 1, o1);
}

// ===========================================================================
extern "C" void kernel_launch(void* const* d_in, const int* in_sizes, int n_in,
                              void* d_out, int out_size) {
    const float4* user4 = (const float4*)d_in[0];
    const float4* item4 = (const float4*)d_in[1];
    const float*  eval  = (const float*) d_in[2];
    const int*    esrc  = (const int*)   d_in[3];
    const int*    edst  = (const int*)   d_in[4];
    float4*       out4  = (float4*)d_out;

    void *pA, *pB, *pC, *pMeta;
    cudaGetSymbolAddress(&pA,    g_bufA);
    cudaGetSymbolAddress(&pB,    g_bufB);
    cudaGetSymbolAddress(&pC,    g_bufC);
    cudaGetSymbolAddress(&pMeta, g_meta);
    uint4* A = (uint4*)pA;
    uint4* B = (uint4*)pB;
    uint4* C = (uint4*)pC;

    const int TB = 256;
    const unsigned group_blocks  = (unsigned)(((long)NUM_NODES * 8 + TB - 1) / TB); // 9375
    const unsigned fuse_blocks   = (NUM_EDGES / 2 + TB - 1) / TB;                   // 3907
    const unsigned assign_blocks = (NUM_NODES + ASSIGN_BS - 1) / ASSIGN_BS;         // 586

    // --- prep ---
    cudaMemsetAsync(pMeta, 0, (NUM_NODES + DEG_BINS + 1) * sizeof(int));
    k_prep_hist      <<<group_blocks, TB>>>(user4, item4, A, esrc);
    k_assign         <<<assign_blocks, ASSIGN_BS>>>();
    k_degscan        <<<1, DEG_BINS>>>();
    k_reorder_permute<<<fuse_blocks, TB>>>((const int2*)esrc, (const int2*)edst,
                                           (const float2*)eval);

    // --- 3 propagation layers ---
    k_layer       <<<group_blocks, TB>>>(A, B);
    k_layer       <<<group_blocks, TB>>>(B, C);
    k_layer3_final<<<group_blocks, TB>>>(C, user4, item4, B, out4);
}